// round 7
// baseline (speedup 1.0000x reference)
#include <cuda_runtime.h>
#include <stdint.h>

#define D_FEAT   256
#define D4       (D_FEAT / 4)     // 64 float4 per x row
#define OUTW     (2 * D_FEAT)     // 512 floats per output row
#define MAX_N    32768
#define MAX_B    8192
#define CAP      128              // slots per destination row (mean deg ~16, max ~45)
#define MAX_SP   65536            // spill capacity (normally 0 used)
#define NT       256

// Scratch (no cudaMalloc allowed) — device globals
__device__ int   g_deg[MAX_N];
__device__ int   g_cntrow[MAX_B];
__device__ int   g_idx64;
__device__ int   g_spill;
__device__ int   g_slots[MAX_B * CAP];
__device__ int2  g_sp_edge[MAX_SP];

// generation-based grid barrier state (monotonic across graph replays)
__device__ int           g_bar_count;
__device__ volatile int  g_bar_gen;

__device__ __forceinline__ void grid_barrier(int nblocks) {
    __syncthreads();
    if (threadIdx.x == 0) {
        int gen = g_bar_gen;
        __threadfence();                       // make prior writes visible
        if (atomicAdd(&g_bar_count, 1) == nblocks - 1) {
            g_bar_count = 0;
            __threadfence();
            g_bar_gen = gen + 1;               // release
        } else {
            while (g_bar_gen == gen) __nanosleep(64);
            __threadfence();                   // acquire
        }
    }
    __syncthreads();
}

__device__ __forceinline__ int load_idx(const void* ei, long long i, int is64) {
    return is64 ? (int)((const long long*)ei)[i] : ((const int*)ei)[i];
}

// ---------------------------------------------------------------------------
__global__ void __launch_bounds__(NT, 4)
k_fused(const void* __restrict__ ei, const float4* __restrict__ x4,
        float4* __restrict__ out4, int E, int n, int batch, int nblocks) {
    const int tid      = blockIdx.x * NT + threadIdx.x;
    const int nthreads = nblocks * NT;

    // ---- Phase A: zero counters, detect index dtype -------------------------
    for (int i = tid; i < n; i += nthreads) g_deg[i] = 0;
    for (int i = tid; i < batch; i += nthreads) g_cntrow[i] = 0;
    if (tid == 0) g_spill = 0;

    if (blockIdx.x == 0) {
        __shared__ int bad;
        if (threadIdx.x == 0) bad = 0;
        __syncthreads();
        const long long* e64 = (const long long*)ei;
        int K = min(E, 2048);
        for (int t = threadIdx.x; t < K; t += NT) {
            long long v = e64[t];
            if (v < 0 || v >= (long long)n) bad = 1;
        }
        __syncthreads();
        if (threadIdx.x == 0) g_idx64 = bad ? 0 : 1;
    }

    grid_barrier(nblocks);

    // ---- Phase B: build deg + slot buckets ----------------------------------
    const int is64 = g_idx64;
    for (int i = tid; i < E; i += nthreads) {
        int src = load_idx(ei, i, is64);
        int dst = load_idx(ei, (long long)E + i, is64);
        atomicAdd(&g_deg[src], 1);
        if (dst < batch) {
            int slot = atomicAdd(&g_cntrow[dst], 1);
            if (slot < CAP) {
                g_slots[dst * CAP + slot] = src;
            } else {
                int p = atomicAdd(&g_spill, 1);
                if (p < MAX_SP) g_sp_edge[p] = make_int2(src, dst);
            }
        }
    }

    grid_barrier(nblocks);

    // ---- Phase C: gather, one warp per output row (grid-strided) ------------
    const int lane   = threadIdx.x & 31;
    const int gwarp  = tid >> 5;
    const int nwarps = nthreads >> 5;

    for (int row = gwarp; row < batch; row += nwarps) {
        int mraw = g_cntrow[row];
        int m = (mraw > CAP) ? CAP : mraw;
        int dr = g_deg[row];
        float disr = (dr > 0) ? rsqrtf((float)dr) : 0.0f;

        float4 a0 = make_float4(0.f, 0.f, 0.f, 0.f);
        float4 a1 = make_float4(0.f, 0.f, 0.f, 0.f);

        const int* srow = g_slots + row * CAP;
        for (int base = 0; base < m; base += 32) {
            int e = base + lane;
            int cnt = min(32, m - base);
            int   psrc = 0;
            float pw   = 0.0f;
            if (e < m) {
                psrc = srow[e];
                pw = rsqrtf((float)g_deg[psrc]) * disr;   // deg[src] >= 1 always
            }
            for (int t = 0; t < cnt; t++) {
                int   s  = __shfl_sync(0xffffffff, psrc, t);
                float ww = __shfl_sync(0xffffffff, pw, t);
                const float4* xs = x4 + (size_t)s * D4;
                float4 v0 = __ldg(&xs[lane]);
                float4 v1 = __ldg(&xs[lane + 32]);
                a0.x += ww * v0.x; a0.y += ww * v0.y; a0.z += ww * v0.z; a0.w += ww * v0.w;
                a1.x += ww * v1.x; a1.y += ww * v1.y; a1.z += ww * v1.z; a1.w += ww * v1.w;
            }
        }

        // Overflow fold (only the owning warp touches its spilled edges; no race).
        if (mraw > CAP) {
            int sp = g_spill;
            if (sp > MAX_SP) sp = MAX_SP;
            for (int base = 0; base < sp; base += 32) {
                int e = base + lane;
                int cnt = min(32, sp - base);
                int   psrc = 0;
                float pw   = 0.0f;
                if (e < sp) {
                    int2 ed = g_sp_edge[e];
                    if (ed.y == row) {
                        psrc = ed.x;
                        pw = rsqrtf((float)g_deg[psrc]) * disr;
                    }
                }
                for (int t = 0; t < cnt; t++) {
                    float ww = __shfl_sync(0xffffffff, pw, t);
                    if (ww == 0.0f) continue;
                    int s = __shfl_sync(0xffffffff, psrc, t);
                    const float4* xs = x4 + (size_t)s * D4;
                    float4 v0 = __ldg(&xs[lane]);
                    float4 v1 = __ldg(&xs[lane + 32]);
                    a0.x += ww * v0.x; a0.y += ww * v0.y; a0.z += ww * v0.z; a0.w += ww * v0.w;
                    a1.x += ww * v1.x; a1.y += ww * v1.y; a1.z += ww * v1.z; a1.w += ww * v1.w;
                }
            }
        }

        const float4* xd = x4 + (size_t)row * D4;
        float4* o = out4 + (size_t)row * (OUTW / 4);
        o[lane]      = __ldg(&xd[lane]);
        o[lane + 32] = __ldg(&xd[lane + 32]);
        o[lane + 64] = a0;
        o[lane + 96] = a1;
    }
}

// ---------------------------------------------------------------------------
extern "C" void kernel_launch(void* const* d_in, const int* in_sizes, int n_in,
                              void* d_out, int out_size) {
    // Identify inputs by element count (robust to metadata ordering).
    int ix = 0, ie = -1;
    for (int i = 1; i < n_in; i++)
        if (in_sizes[i] > in_sizes[ix]) ix = i;
    for (int i = 0; i < n_in; i++) {
        if (i == ix || in_sizes[i] <= 1) continue;
        if (ie < 0 || in_sizes[i] > in_sizes[ie]) ie = i;
    }
    if (ie < 0) ie = (ix == 0) ? 1 : 0;

    const float* x  = (const float*)d_in[ix];
    const void*  ei = d_in[ie];

    int n     = in_sizes[ix] / D_FEAT;         // 20000
    int E     = in_sizes[ie] / 2;              // 320000
    int batch = out_size / OUTW;               // 4096

    // Co-resident grid: 4 CTAs/SM guaranteed by __launch_bounds__(256, 4).
    static int smCount = 0;
    if (smCount == 0) {
        if (cudaDeviceGetAttribute(&smCount, cudaDevAttrMultiProcessorCount, 0)
            != cudaSuccess || smCount <= 0)
            smCount = 148;
    }
    int nblocks = smCount * 4;

    k_fused<<<nblocks, NT>>>(ei, (const float4*)x, (float4*)d_out,
                             E, n, batch, nblocks);
}